// round 5
// baseline (speedup 1.0000x reference)
#include <cuda_runtime.h>
#include <cstdint>

#define BB   16
#define CC   3
#define HH   512
#define WW   512
#define CUT  224
#define CUTN 32

#define THREADS 224
#define RPI 4                 // rows per iteration (one 56-thread group per row)
#define ROWS_PER_BLOCK 56
#define NITER (ROWS_PER_BLOCK / RPI)   // 14
#define SROW 132              // float4 per smem row (>= max nvec 129, padded)

__global__ __launch_bounds__(THREADS) void make_cutouts_kernel(
    const float* __restrict__ x,
    const int*   __restrict__ sizes,
    const int*   __restrict__ offx,
    const int*   __restrict__ offy,
    float*       __restrict__ out)
{
    const int n     = blockIdx.x;   // cut index [0,32)
    const int bc    = blockIdx.y;   // plane     [0,48)
    const int chunk = blockIdx.z;   // 56-row chunk [0,4)

    const int tid  = threadIdx.x;
    const int jg   = tid % 56;      // lane within row group / output col group
    const int rsub = tid / 56;      // which of the 4 rows this thread serves

    __shared__ float4 s[2][RPI][SROW];

    const int sz = sizes[n];
    const int ox = offx[n];
    const int oy = offy[n];

    const int base = ox & ~3;                  // 16B-aligned start col
    const int b4   = base >> 2;                // in float4 units
    const int nvec = ((ox + sz) - base + 3) >> 2;   // float4 count, <= 129 (end <= 512)

    // Gather column offsets (floats, relative to base) for this thread's 4 output cols
    const int c0 = jg * 4;
    const int rb = ox - base;
    const int g0 = rb + ( c0      * sz) / CUT;
    const int g1 = rb + ((c0 + 1) * sz) / CUT;
    const int g2 = rb + ((c0 + 2) * sz) / CUT;
    const int g3 = rb + ((c0 + 3) * sz) / CUT;

    const float* __restrict__ xplane = x + (size_t)bc * (HH * WW);
    float4* __restrict__ oplane =
        (float4*)(out + ((size_t)n * (BB * CC) + bc) * (size_t)(CUT * CUT));

    const int i_base = chunk * ROWS_PER_BLOCK + rsub;

    // ---- prefetch iteration 0 into registers (coalesced float4 loads) ----
    float4 v0, v1, v2;
    {
        const int yi = oy + (i_base * sz) / CUT;
        const float4* rowp = (const float4*)(xplane + (size_t)yi * WW) + b4;
        if (jg       < nvec) v0 = __ldg(rowp + jg);
        if (jg + 56  < nvec) v1 = __ldg(rowp + jg + 56);
        if (jg + 112 < nvec) v2 = __ldg(rowp + jg + 112);
    }

    #pragma unroll 2
    for (int it = 0; it < NITER; ++it) {
        const int buf = it & 1;

        // stage prefetched row into smem
        if (jg       < nvec) s[buf][rsub][jg      ] = v0;
        if (jg + 56  < nvec) s[buf][rsub][jg +  56] = v1;
        if (jg + 112 < nvec) s[buf][rsub][jg + 112] = v2;

        // prefetch next iteration's row (overlaps with gather below)
        if (it + 1 < NITER) {
            const int yi = oy + ((i_base + (it + 1) * RPI) * sz) / CUT;
            const float4* rowp = (const float4*)(xplane + (size_t)yi * WW) + b4;
            if (jg       < nvec) v0 = __ldg(rowp + jg);
            if (jg + 56  < nvec) v1 = __ldg(rowp + jg + 56);
            if (jg + 112 < nvec) v2 = __ldg(rowp + jg + 112);
        }

        __syncthreads();

        // gather current row from smem, coalesced streaming store
        const int i = i_base + it * RPI;
        const float* srow = (const float*)s[buf][rsub];
        float4 o;
        o.x = srow[g0];
        o.y = srow[g1];
        o.z = srow[g2];
        o.w = srow[g3];
        __stcs(&oplane[(size_t)i * 56 + jg], o);
        // no trailing sync needed: next iteration writes buf^1, last read 2 iters ago,
        // ordered by the syncthreads above
    }
}

extern "C" void kernel_launch(void* const* d_in, const int* in_sizes, int n_in,
                              void* d_out, int out_size)
{
    const float* x     = (const float*)d_in[0];
    const int*   sizes = (const int*)d_in[1];
    const int*   ox    = (const int*)d_in[2];
    const int*   oy    = (const int*)d_in[3];
    float*       out   = (float*)d_out;

    dim3 grid(CUTN, BB * CC, CUT / ROWS_PER_BLOCK);
    dim3 block(THREADS);
    make_cutouts_kernel<<<grid, block>>>(x, sizes, ox, oy, out);
}

// round 11
// speedup vs baseline: 1.3230x; 1.3230x over previous
#include <cuda_runtime.h>
#include <cstdint>

#define BB   16
#define CC   3
#define HH   512
#define WW   512
#define CUT  224
#define CUTN 32

#define THREADS 224
#define ROWS_PER_BLOCK 56
#define RB 8   // rows batched per iteration (MLP depth per thread)

__global__ __launch_bounds__(THREADS) void make_cutouts_kernel(
    const float* __restrict__ x,
    const int*   __restrict__ sizes,
    const int*   __restrict__ offx,
    const int*   __restrict__ offy,
    float*       __restrict__ out)
{
    const int n     = blockIdx.x;   // cut index [0,32)
    const int bc    = blockIdx.y;   // plane     [0,48)
    const int chunk = blockIdx.z;   // row chunk [0,4)
    const int j     = threadIdx.x;  // output column (lane-contiguous -> coalesced reads)

    const int sz = sizes[n];
    const int ox = offx[n];
    const int oy = offy[n];

    // This thread's gather column (lanes stride sz/224 in [1, 2.29] floats)
    const int xj = ox + (j * sz) / CUT;

    const float* __restrict__ xplane = x + (size_t)bc * (HH * WW) + xj;
    float* __restrict__ oplane =
        out + ((size_t)n * (BB * CC) + bc) * (size_t)(CUT * CUT) + j;

    const int i0 = chunk * ROWS_PER_BLOCK;

    // 7 iterations x 8 independent rows: all loads issued before any store -> MLP=8/thread
    for (int rb = 0; rb < ROWS_PER_BLOCK; rb += RB) {
        const int i = i0 + rb;

        float v[RB];
        #pragma unroll
        for (int k = 0; k < RB; ++k) {
            const int yk = oy + ((i + k) * sz) / CUT;
            v[k] = __ldg(xplane + (size_t)yk * WW);
        }

        // Streaming stores: output is write-once/dead -> evict-first in L2
        #pragma unroll
        for (int k = 0; k < RB; ++k) {
            __stcs(oplane + (size_t)(i + k) * CUT, v[k]);
        }
    }
}

extern "C" void kernel_launch(void* const* d_in, const int* in_sizes, int n_in,
                              void* d_out, int out_size)
{
    const float* x     = (const float*)d_in[0];
    const int*   sizes = (const int*)d_in[1];
    const int*   ox    = (const int*)d_in[2];
    const int*   oy    = (const int*)d_in[3];
    float*       out   = (float*)d_out;

    dim3 grid(CUTN, BB * CC, CUT / ROWS_PER_BLOCK);
    dim3 block(THREADS);
    make_cutouts_kernel<<<grid, block>>>(x, sizes, ox, oy, out);
}

// round 15
// speedup vs baseline: 1.4666x; 1.1086x over previous
#include <cuda_runtime.h>
#include <cstdint>

#define BB   16
#define CC   3
#define HH   512
#define WW   512
#define CUT  224
#define CUTN 32

#define BAND    8
#define NBANDS  (HH / BAND)     // 64
#define THREADS 256
#define NWARPS  (THREADS / 32)  // 8

// Block = (input-row band, plane bc). All cuts sampling rows in this band are
// processed here, so the band (8 rows x 2KB = 16KB) stays L1-resident and the
// 32x cross-cut re-reads of x hit L1 instead of hammering L2.
__global__ __launch_bounds__(THREADS) void make_cutouts_kernel(
    const float* __restrict__ x,
    const int*   __restrict__ sizes,
    const int*   __restrict__ offx,
    const int*   __restrict__ offy,
    float*       __restrict__ out)
{
    const int band = blockIdx.x;          // [0, 64)
    const int bc   = blockIdx.y;          // [0, 48)
    const int y0   = band * BAND;

    __shared__ int s_sz[CUTN], s_ox[CUTN], s_oy[CUTN], s_ilo[CUTN];
    __shared__ int s_pfx[CUTN + 1];

    const int tid = threadIdx.x;

    // Per-cut: which output rows i have yidx(i) = oy + i*sz/224 in [y0, y0+BAND)?
    if (tid < CUTN) {
        const int sz = sizes[tid];
        const int ox = offx[tid];
        const int oy = offy[tid];
        s_sz[tid] = sz; s_ox[tid] = ox; s_oy[tid] = oy;

        const int a  = y0 - oy;
        const int A  = a > 0 ? a : 0;
        const int Bb = a + BAND;

        int ilo = (CUT * A + sz - 1) / sz;          // first i with floor(i*sz/224) >= A
        if (ilo > CUT) ilo = CUT;
        int ihi = 0;
        if (Bb > 0) {
            ihi = (CUT * Bb + sz - 1) / sz;         // first i with floor(i*sz/224) >= Bb
            if (ihi > CUT) ihi = CUT;
        }
        int cnt = ihi - ilo;
        if (cnt < 0) cnt = 0;
        s_ilo[tid]     = ilo;
        s_pfx[tid + 1] = cnt;                       // counts, prefixed below
    }
    __syncthreads();
    if (tid == 0) {
        int acc = 0;
        s_pfx[0] = 0;
        #pragma unroll
        for (int k = 0; k < CUTN; ++k) { acc += s_pfx[k + 1]; s_pfx[k + 1] = acc; }
    }
    __syncthreads();

    const int total = s_pfx[CUTN];
    const int wid   = tid >> 5;
    const int lane  = tid & 31;

    const float* __restrict__ xplane = x + (size_t)bc * (HH * WW);

    // Warps take tasks round-robin; t increases per warp so the cut lookup is
    // an amortized-O(1) forward scan over the prefix array.
    int cur = 0;
    for (int t = wid; t < total; t += NWARPS) {
        while (t >= s_pfx[cur + 1]) ++cur;
        const int n  = cur;
        const int sz = s_sz[n];
        const int ox = s_ox[n];
        const int oy = s_oy[n];
        const int i  = s_ilo[n] + (t - s_pfx[n]);
        const int y  = oy + (i * sz) / CUT;

        const float* __restrict__ row = xplane + (size_t)y * WW;
        float* __restrict__ orow =
            out + ((size_t)(n * (BB * CC) + bc)) * (CUT * CUT) + (size_t)i * CUT;

        // Batch the 7 gathers (L1-hot band) ahead of the 7 coalesced stores.
        float v[7];
        #pragma unroll
        for (int c = 0; c < 7; ++c) {
            const int col = c * 32 + lane;
            const int xi  = ox + (col * sz) / CUT;
            v[c] = row[xi];
        }
        #pragma unroll
        for (int c = 0; c < 7; ++c) {
            __stcs(orow + c * 32 + lane, v[c]);     // dead data -> evict-first
        }
    }
}

extern "C" void kernel_launch(void* const* d_in, const int* in_sizes, int n_in,
                              void* d_out, int out_size)
{
    const float* x     = (const float*)d_in[0];
    const int*   sizes = (const int*)d_in[1];
    const int*   ox    = (const int*)d_in[2];
    const int*   oy    = (const int*)d_in[3];
    float*       out   = (float*)d_out;

    dim3 grid(NBANDS, BB * CC);
    dim3 block(THREADS);
    make_cutouts_kernel<<<grid, block>>>(x, sizes, ox, oy, out);
}